// round 3
// baseline (speedup 1.0000x reference)
#include <cuda_runtime.h>

#define HH 768
#define NN 64
#define LSEQ 2048
#define BB 4
#define Q 64
#define NCH (LSEQ / Q)        // 32 chunks
#define BPB 2                 // batches per block
#define COLS (BPB * NCH)      // 64 columns per block
#define NBLK (HH * (BB / BPB))// 1536 blocks
#define NTHREADS 256

typedef unsigned long long ull;

// ---- f32x2 helpers ----
__device__ __forceinline__ ull pk2(float lo, float hi) {
    ull r; asm("mov.b64 %0, {%1, %2};" : "=l"(r) : "f"(lo), "f"(hi)); return r;
}
__device__ __forceinline__ void upk2(ull v, float& lo, float& hi) {
    asm("mov.b64 {%0, %1}, %2;" : "=f"(lo), "=f"(hi) : "l"(v));
}
__device__ __forceinline__ ull f2fma(ull a, ull b, ull c) {
    ull d; asm("fma.rn.f32x2 %0, %1, %2, %3;" : "=l"(d) : "l"(a), "l"(b), "l"(c)); return d;
}

// Per-(h,n) discretized params
__device__ float2 g_A[HH * NN];   // A_bar
__device__ float2 g_Bb[HH * NN];  // B_bar
__device__ float2 g_C[HH * NN];   // C
__device__ float2 g_K[HH * NN];   // C * B_bar

// ---- Shared memory layout (floats). Row strides padded to 16B multiples. ----
#define ST68  68            // 64-col rows
#define ST132 132           // 128-col rows
#define OFF_PS   0                      // P: 65x132=8580 / S: 128x68=8704 (union)
#define SZ_PS    8704
#define OFF_U    (OFF_PS + SZ_PS)      // U: 64x68
#define OFF_TT   (OFF_U + 64 * ST68)   // TT: 64x68
#define OFF_WT   (OFF_TT + 64 * ST68)  // WT: 64x132
#define OFF_VT   (OFF_WT + 64 * ST132) // VT: 128x68
#define OFF_Y    (OFF_VT + 128 * ST68) // Y: 64x68
#define OFF_KL   (OFF_Y + 64 * ST68)   // k[l]: 64
#define OFF_AQ   (OFF_KL + 64)         // A^Q: 128
#define OFF_BB   (OFF_AQ + 128)        // Bbar: 128
#define OFF_CC   (OFF_BB + 128)        // C: 128
#define OFF_KM   (OFF_CC + 128)        // K modes: 128
#define SMEM_FLOATS (OFF_KM + 128)
#define SMEM_BYTES (SMEM_FLOATS * 4)

// ---------------- Kernel 0: ZOH discretization ----------------
__global__ void setup_kernel(const float* __restrict__ log_neg_real,
                             const float* __restrict__ imag,
                             const float* __restrict__ B_re,
                             const float* __restrict__ B_im,
                             const float* __restrict__ C_re,
                             const float* __restrict__ C_im,
                             const float* __restrict__ log_dt) {
    int idx = blockIdx.x * blockDim.x + threadIdx.x;
    if (idx >= HH * NN) return;
    int h = idx >> 6;

    float lre = -expf(log_neg_real[idx]);
    float lim = imag[idx];
    float dt  = expf(log_dt[h]);

    float zre = lre * dt, zim = lim * dt;
    float ea = expf(zre);
    float sn, cs; sincosf(zim, &sn, &cs);
    float Are = ea * cs, Aim = ea * sn;

    float dre = Are - 1.0f, dim = Aim;
    float den = lre * lre + lim * lim;
    float ire = lre / den, iim = -lim / den;
    float tre = dre * ire - dim * iim;
    float tim = dre * iim + dim * ire;
    float br = B_re[idx], bi = B_im[idx];
    float Bbre = tre * br - tim * bi;
    float Bbim = tre * bi + tim * br;

    float cr = C_re[idx], ci = C_im[idx];

    g_A[idx]  = make_float2(Are, Aim);
    g_Bb[idx] = make_float2(Bbre, Bbim);
    g_C[idx]  = make_float2(cr, ci);
    g_K[idx]  = make_float2(cr * Bbre - ci * Bbim, cr * Bbim + ci * Bbre);
}

// ---------------- Kernel 1: chunked SSM as 3 shared-memory GEMMs ----------------
__global__ void __launch_bounds__(NTHREADS, 1)
ssm_chunk_kernel(const float* __restrict__ u,
                 const float* __restrict__ Dv,
                 float* __restrict__ y) {
    extern __shared__ float sm[];
    const int h  = blockIdx.x >> 1;
    const int b0 = (blockIdx.x & 1) * BPB;
    const int tid = threadIdx.x;

    float* P  = sm + OFF_PS;   // powers, stride ST132
    float* S  = sm + OFF_PS;   // states (reuses P region), stride ST68
    float* U  = sm + OFF_U;
    float* TT = sm + OFF_TT;
    float* WT = sm + OFF_WT;
    float* VT = sm + OFF_VT;
    float* Ysm= sm + OFF_Y;
    float* kl = sm + OFF_KL;
    float* aq = sm + OFF_AQ;
    float* bbs= sm + OFF_BB;
    float* ccs= sm + OFF_CC;
    float* kms= sm + OFF_KM;

    // ---- Phase A: per-mode params + powers P[l] = A^l, l = 0..Q ----
    if (tid < NN) {
        const int n = tid;
        float2 a = g_A[h * NN + n];
        float2 bb = g_Bb[h * NN + n];
        float2 cc = g_C[h * NN + n];
        float2 kk = g_K[h * NN + n];
        bbs[2 * n] = bb.x; bbs[2 * n + 1] = bb.y;
        ccs[2 * n] = cc.x; ccs[2 * n + 1] = cc.y;
        kms[2 * n] = kk.x; kms[2 * n + 1] = kk.y;
        float pre = 1.0f, pim = 0.0f;
        #pragma unroll 1
        for (int l = 0; l <= Q; ++l) {
            P[l * ST132 + 2 * n]     = pre;
            P[l * ST132 + 2 * n + 1] = pim;
            float nre = pre * a.x - pim * a.y;
            float nim = pre * a.y + pim * a.x;
            pre = nre; pim = nim;
        }
    }
    __syncthreads();

    // ---- Phase B: k[l] = Re(sum_n K_n A^l); save A^Q ----
    if (tid < Q) {
        const int l = tid;
        float acc = 0.0f;
        #pragma unroll 4
        for (int n = 0; n < NN; ++n)
            acc += kms[2 * n] * P[l * ST132 + 2 * n]
                 - kms[2 * n + 1] * P[l * ST132 + 2 * n + 1];
        kl[l] = acc;
    } else if (tid >= 128) {
        int r = tid - 128;
        aq[r] = P[Q * ST132 + r];
    }
    __syncthreads();

    // ---- Phase C: build TT, WT, VT ----
    for (int idx = tid; idx < Q * Q; idx += NTHREADS) {
        int k = idx >> 6, i = idx & 63;
        TT[k * ST68 + i] = (i >= k) ? kl[i - k] : 0.0f;
    }
    for (int idx = tid; idx < Q * NN; idx += NTHREADS) {
        int k = idx >> 6, n = idx & 63;
        float pre = P[(Q - 1 - k) * ST132 + 2 * n];
        float pim = P[(Q - 1 - k) * ST132 + 2 * n + 1];
        float br = bbs[2 * n], bi = bbs[2 * n + 1];
        WT[k * ST132 + 2 * n]     = pre * br - pim * bi;
        WT[k * ST132 + 2 * n + 1] = pre * bi + pim * br;
    }
    for (int idx = tid; idx < NN * Q; idx += NTHREADS) {
        int n = idx >> 6, i = idx & 63;
        float pre = P[(i + 1) * ST132 + 2 * n];
        float pim = P[(i + 1) * ST132 + 2 * n + 1];
        float cr = ccs[2 * n], ci = ccs[2 * n + 1];
        VT[(2 * n) * ST68 + i]     =  cr * pre - ci * pim;
        VT[(2 * n + 1) * ST68 + i] = -(cr * pim + ci * pre);
    }

    // ---- Phase D: load U (2 batches x 2048, reshaped to [j][col]) ----
    const float4* u4 = (const float4*)u;
    for (int w = tid; w < BPB * (LSEQ / 4); w += NTHREADS) {
        int bloc = w >> 9;            // 0..1
        int l4 = w & 511;
        int l = l4 * 4;
        int j = l & 63, c = l >> 6;
        int col = bloc * NCH + c;
        float4 v = u4[((size_t)(b0 + bloc) * HH + h) * (LSEQ / 4) + l4];
        U[(j + 0) * ST68 + col] = v.x;
        U[(j + 1) * ST68 + col] = v.y;
        U[(j + 2) * ST68 + col] = v.z;
        U[(j + 3) * ST68 + col] = v.w;
    }
    __syncthreads();

    // ---- Phase E (G1): S_raw[r][col] = sum_k WT[k][r] * U[k][col]  (128x64) ----
    {
        const int rg = tid >> 4;       // 0..15 -> rows r0..r0+7
        const int cg = tid & 15;       // 0..15 -> cols c0..c0+3
        const int r0 = rg * 8, c0 = cg * 4;
        ull acc[4][4];
        #pragma unroll
        for (int c = 0; c < 4; ++c)
            #pragma unroll
            for (int rp = 0; rp < 4; ++rp) acc[c][rp] = 0ull;

        #pragma unroll 4
        for (int k = 0; k < Q; ++k) {
            ulonglong2 w01 = *(const ulonglong2*)&WT[k * ST132 + r0];
            ulonglong2 w23 = *(const ulonglong2*)&WT[k * ST132 + r0 + 4];
            float4 uv = *(const float4*)&U[k * ST68 + c0];
            const float uf[4] = {uv.x, uv.y, uv.z, uv.w};
            #pragma unroll
            for (int c = 0; c < 4; ++c) {
                ull ub = pk2(uf[c], uf[c]);
                acc[c][0] = f2fma(w01.x, ub, acc[c][0]);
                acc[c][1] = f2fma(w01.y, ub, acc[c][1]);
                acc[c][2] = f2fma(w23.x, ub, acc[c][2]);
                acc[c][3] = f2fma(w23.y, ub, acc[c][3]);
            }
        }
        __syncthreads();   // P region no longer needed; S overwrites it
        #pragma unroll
        for (int c = 0; c < 4; ++c)
            #pragma unroll
            for (int rp = 0; rp < 4; ++rp) {
                float lo, hi; upk2(acc[c][rp], lo, hi);
                S[(r0 + 2 * rp) * ST68 + (c0 + c)]     = lo;
                S[(r0 + 2 * rp + 1) * ST68 + (c0 + c)] = hi;
            }
    }
    __syncthreads();

    // ---- Phase F: sequential chunk-state combine (in place: S -> incoming states) ----
    if (tid < 128) {
        const int b2 = tid >> 6;          // local batch
        const int n  = tid & 63;
        const float ar = aq[2 * n], ai = aq[2 * n + 1];
        float cre = 0.0f, cim = 0.0f;     // s_in for chunk 0 is zero
        #pragma unroll 1
        for (int c = 0; c < NCH; ++c) {
            const int col = b2 * NCH + c;
            float rre = S[(2 * n) * ST68 + col];
            float rim = S[(2 * n + 1) * ST68 + col];
            S[(2 * n) * ST68 + col]     = cre;
            S[(2 * n + 1) * ST68 + col] = cim;
            float nre = ar * cre - ai * cim + rre;
            float nim = ar * cim + ai * cre + rim;
            cre = nre; cim = nim;
        }
    }
    __syncthreads();

    // ---- Phase G (G2): Y = TT^T @ U + VT^T @ S  (64x64) ----
    {
        const int rg = tid >> 4;       // rows i0..i0+3
        const int cg = tid & 15;       // cols c0..c0+3
        const int i0 = rg * 4, c0 = cg * 4;
        ull acc[4][2];
        #pragma unroll
        for (int c = 0; c < 4; ++c) { acc[c][0] = 0ull; acc[c][1] = 0ull; }

        #pragma unroll 4
        for (int k = 0; k < Q; ++k) {
            ulonglong2 tfr = *(const ulonglong2*)&TT[k * ST68 + i0];
            float4 uv = *(const float4*)&U[k * ST68 + c0];
            const float uf[4] = {uv.x, uv.y, uv.z, uv.w};
            #pragma unroll
            for (int c = 0; c < 4; ++c) {
                ull ub = pk2(uf[c], uf[c]);
                acc[c][0] = f2fma(tfr.x, ub, acc[c][0]);
                acc[c][1] = f2fma(tfr.y, ub, acc[c][1]);
            }
        }
        #pragma unroll 4
        for (int r = 0; r < 2 * NN; ++r) {
            ulonglong2 vfr = *(const ulonglong2*)&VT[r * ST68 + i0];
            float4 sv = *(const float4*)&S[r * ST68 + c0];
            const float sf[4] = {sv.x, sv.y, sv.z, sv.w};
            #pragma unroll
            for (int c = 0; c < 4; ++c) {
                ull sb = pk2(sf[c], sf[c]);
                acc[c][0] = f2fma(vfr.x, sb, acc[c][0]);
                acc[c][1] = f2fma(vfr.y, sb, acc[c][1]);
            }
        }
        #pragma unroll
        for (int c = 0; c < 4; ++c)
            #pragma unroll
            for (int rp = 0; rp < 2; ++rp) {
                float lo, hi; upk2(acc[c][rp], lo, hi);
                Ysm[(i0 + 2 * rp) * ST68 + (c0 + c)]     = lo;
                Ysm[(i0 + 2 * rp + 1) * ST68 + (c0 + c)] = hi;
            }
    }
    __syncthreads();

    // ---- Phase H: output with D*u, coalesced ----
    const float Dh = Dv[h];
    float4* y4 = (float4*)y;
    for (int w = tid; w < BPB * (LSEQ / 4); w += NTHREADS) {
        int bloc = w >> 9;
        int l4 = w & 511;
        int l = l4 * 4;
        int j = l & 63, c = l >> 6;
        int col = bloc * NCH + c;
        float4 v;
        v.x = Ysm[(j + 0) * ST68 + col] + Dh * U[(j + 0) * ST68 + col];
        v.y = Ysm[(j + 1) * ST68 + col] + Dh * U[(j + 1) * ST68 + col];
        v.z = Ysm[(j + 2) * ST68 + col] + Dh * U[(j + 2) * ST68 + col];
        v.w = Ysm[(j + 3) * ST68 + col] + Dh * U[(j + 3) * ST68 + col];
        y4[((size_t)(b0 + bloc) * HH + h) * (LSEQ / 4) + l4] = v;
    }
}

extern "C" void kernel_launch(void* const* d_in, const int* in_sizes, int n_in,
                              void* d_out, int out_size) {
    const float* u    = (const float*)d_in[0];
    const float* lnr  = (const float*)d_in[1];
    const float* im   = (const float*)d_in[2];
    const float* B_re = (const float*)d_in[3];
    const float* B_im = (const float*)d_in[4];
    const float* C_re = (const float*)d_in[5];
    const float* C_im = (const float*)d_in[6];
    const float* ldt  = (const float*)d_in[7];
    const float* Dv   = (const float*)d_in[8];
    float* y = (float*)d_out;

    static int attr_done = 0;
    if (!attr_done) {
        cudaFuncSetAttribute(ssm_chunk_kernel,
                             cudaFuncAttributeMaxDynamicSharedMemorySize, SMEM_BYTES);
        attr_done = 1;
    }

    setup_kernel<<<(HH * NN + 255) / 256, 256>>>(lnr, im, B_re, B_im, C_re, C_im, ldt);
    ssm_chunk_kernel<<<NBLK, NTHREADS, SMEM_BYTES>>>(u, Dv, y);
}

// round 6
// speedup vs baseline: 1.8060x; 1.8060x over previous
#include <cuda_runtime.h>
#include <cuda_bf16.h>
#include <cstdint>

#define HH 768
#define NN 64
#define LSEQ 2048
#define BB 4
#define Q 64
#define NCH 32
#define NTHREADS 256
#define NBLK HH

typedef unsigned int u32;
typedef unsigned short u16;

// ---------------- smem layout (bytes) ----------------
// K64 panels: 64 bf16/row, stride 144 B (16B-aligned rows, 144%128==16 -> ldmatrix conflict-free)
// K128 panels: 128 bf16/row, stride 272 B
#define SB64 144
#define SB128 272
#define OFF_AQ   0            // 128 f32
#define OFF_KL   512          // 64 f32
#define OFF_BBS  768          // 128 f32
#define OFF_CCS  1280         // 128 f32
#define OFF_KMS  1792         // 128 f32
#define OFF_UH   4096                      // 128 x 144 = 18432
#define OFF_UL   (OFF_UH + 18432)          // 22528
#define OFF_STH  (OFF_UL + 18432)          // 40960: 128 x 272 = 34816
#define OFF_STL  (OFF_STH + 34816)         // 75776
#define OFF_P    (OFF_STL + 34816)         // 110592: fp32 powers 65 x 130 f
#define PSTR     130
#define OFF_X    (OFF_P + 33824)           // 144416: union region
// X contents over time:
//   C1/G1:  Wh @ X+0 (18432), Wl @ X+18432
//   R fp32: @ X+0, 128 cols x 132 f (67584)
//   C2/G2:  Th @ X+0 (9216), Tl @ X+9216, Vh @ X+18432 (17408), Vl @ X+35840
#define OFF_WH   (OFF_X)
#define OFF_WL   (OFF_X + 18432)
#define OFF_R    (OFF_X)
#define RSTR     132
#define OFF_TH   (OFF_X)
#define OFF_TL   (OFF_X + 9216)
#define OFF_VH   (OFF_X + 18432)
#define OFF_VL   (OFF_X + 35840)
#define SMEM_BYTES (OFF_X + 67584)         // 212000

// ---------------- helpers ----------------
__device__ __forceinline__ u32 smem_u32(const void* p) {
    u32 a;
    asm("{ .reg .u64 t; cvta.to.shared.u64 t, %1; cvt.u32.u64 %0, t; }" : "=r"(a) : "l"(p));
    return a;
}
__device__ __forceinline__ void ldsm_x4(u32 addr, u32& r0, u32& r1, u32& r2, u32& r3) {
    asm volatile("ldmatrix.sync.aligned.m8n8.x4.shared.b16 {%0,%1,%2,%3}, [%4];"
                 : "=r"(r0), "=r"(r1), "=r"(r2), "=r"(r3) : "r"(addr));
}
__device__ __forceinline__ void ldsm_x2(u32 addr, u32& r0, u32& r1) {
    asm volatile("ldmatrix.sync.aligned.m8n8.x2.shared.b16 {%0,%1}, [%2];"
                 : "=r"(r0), "=r"(r1) : "r"(addr));
}
__device__ __forceinline__ void mma16816(float* d, u32 a0, u32 a1, u32 a2, u32 a3,
                                         u32 b0, u32 b1) {
    asm volatile("mma.sync.aligned.m16n8k16.row.col.f32.bf16.bf16.f32 "
                 "{%0,%1,%2,%3}, {%4,%5,%6,%7}, {%8,%9}, {%0,%1,%2,%3};"
                 : "+f"(d[0]), "+f"(d[1]), "+f"(d[2]), "+f"(d[3])
                 : "r"(a0), "r"(a1), "r"(a2), "r"(a3), "r"(b0), "r"(b1));
}
__device__ __forceinline__ void split_bf(float v, u16& h, u16& l) {
    __nv_bfloat16 bh = __float2bfloat16(v);
    float rem = v - __bfloat162float(bh);
    __nv_bfloat16 bl = __float2bfloat16(rem);
    h = __bfloat16_as_ushort(bh);
    l = __bfloat16_as_ushort(bl);
}

// Per-(h,n) discretized params
__device__ float2 g_A[HH * NN];
__device__ float2 g_Bb[HH * NN];
__device__ float2 g_C[HH * NN];
__device__ float2 g_K[HH * NN];

// ---------------- Kernel 0: ZOH discretization ----------------
__global__ void setup_kernel(const float* __restrict__ log_neg_real,
                             const float* __restrict__ imag,
                             const float* __restrict__ B_re,
                             const float* __restrict__ B_im,
                             const float* __restrict__ C_re,
                             const float* __restrict__ C_im,
                             const float* __restrict__ log_dt) {
    int idx = blockIdx.x * blockDim.x + threadIdx.x;
    if (idx >= HH * NN) return;
    int h = idx >> 6;

    float lre = -expf(log_neg_real[idx]);
    float lim = imag[idx];
    float dt  = expf(log_dt[h]);

    float zre = lre * dt, zim = lim * dt;
    float ea = expf(zre);
    float sn, cs; sincosf(zim, &sn, &cs);
    float Are = ea * cs, Aim = ea * sn;

    float dre = Are - 1.0f, dim = Aim;
    float den = lre * lre + lim * lim;
    float ire = lre / den, iim = -lim / den;
    float tre = dre * ire - dim * iim;
    float tim = dre * iim + dim * ire;
    float br = B_re[idx], bi = B_im[idx];
    float Bbre = tre * br - tim * bi;
    float Bbim = tre * bi + tim * br;

    float cr = C_re[idx], ci = C_im[idx];

    g_A[idx]  = make_float2(Are, Aim);
    g_Bb[idx] = make_float2(Bbre, Bbim);
    g_C[idx]  = make_float2(cr, ci);
    g_K[idx]  = make_float2(cr * Bbre - ci * Bbim, cr * Bbim + ci * Bbre);
}

// ---------------- Kernel 1: chunked SSM on HMMA (mma.sync) ----------------
__global__ void __launch_bounds__(NTHREADS)
ssm_mma_kernel(const float* __restrict__ u,
               const float* __restrict__ Dv,
               float* __restrict__ y) {
    extern __shared__ char smem[];
    const u32 sbase = smem_u32(smem);
    const int tid = threadIdx.x;
    const int wid = tid >> 5;
    const int lane = tid & 31;
    const int h = blockIdx.x;

    float* aq  = (float*)(smem + OFF_AQ);
    float* kl  = (float*)(smem + OFF_KL);
    float* bbs = (float*)(smem + OFF_BBS);
    float* ccs = (float*)(smem + OFF_CCS);
    float* kms = (float*)(smem + OFF_KMS);
    float* P   = (float*)(smem + OFF_P);

    // ---- Phase A: powers P[l] = A^l (l=0..64), params to smem ----
    if (tid < NN) {
        const int n = tid;
        float2 a  = g_A[h * NN + n];
        float2 bb = g_Bb[h * NN + n];
        float2 cc = g_C[h * NN + n];
        float2 kk = g_K[h * NN + n];
        bbs[2 * n] = bb.x; bbs[2 * n + 1] = bb.y;
        ccs[2 * n] = cc.x; ccs[2 * n + 1] = cc.y;
        kms[2 * n] = kk.x; kms[2 * n + 1] = kk.y;
        float pre = 1.0f, pim = 0.0f;
        #pragma unroll 1
        for (int l = 0; l <= Q; ++l) {
            P[l * PSTR + 2 * n]     = pre;
            P[l * PSTR + 2 * n + 1] = pim;
            float nre = pre * a.x - pim * a.y;
            float nim = pre * a.y + pim * a.x;
            pre = nre; pim = nim;
        }
    }
    // ---- Phase D (concurrent): load u, split into Uh/Ul ([col][j]) ----
    {
        const float4* u4 = (const float4*)u;
        for (int idx = tid; idx < 2048; idx += NTHREADS) {
            int b = idx >> 9, l4 = idx & 511;
            float4 v = u4[((size_t)b * HH + h) * 512 + (u32)l4];
            int c = (l4 >> 4) & 31, j = (l4 & 15) * 4;
            int col = b * 32 + c;
            u16 hs[4], ls[4];
            split_bf(v.x, hs[0], ls[0]);
            split_bf(v.y, hs[1], ls[1]);
            split_bf(v.z, hs[2], ls[2]);
            split_bf(v.w, hs[3], ls[3]);
            u32 off = (u32)(col * SB64 + j * 2);
            *(uint2*)(smem + OFF_UH + off) = make_uint2((u32)hs[0] | ((u32)hs[1] << 16),
                                                        (u32)hs[2] | ((u32)hs[3] << 16));
            *(uint2*)(smem + OFF_UL + off) = make_uint2((u32)ls[0] | ((u32)ls[1] << 16),
                                                        (u32)ls[2] | ((u32)ls[3] << 16));
        }
    }
    __syncthreads();

    // ---- Phase B: kl[l] = Re(sum K A^l); aq = A^Q ----
    if (tid < Q) {
        float acc = 0.0f;
        #pragma unroll 8
        for (int n = 0; n < NN; ++n)
            acc += kms[2 * n] * P[tid * PSTR + 2 * n]
                 - kms[2 * n + 1] * P[tid * PSTR + 2 * n + 1];
        kl[tid] = acc;
    } else if (tid < 192) {
        int r = tid - 64;
        aq[r] = P[Q * PSTR + r];
    }
    // ---- Phase C1: build W (h/l): W[r][j], r=2n/2n+1 <- Re/Im(A^{63-j} Bbar) ----
    for (int idx = tid; idx < 128 * 64; idx += NTHREADS) {
        int r = idx >> 6, j = idx & 63, n = r >> 1;
        float pre = P[(Q - 1 - j) * PSTR + 2 * n];
        float pim = P[(Q - 1 - j) * PSTR + 2 * n + 1];
        float br = bbs[2 * n], bi = bbs[2 * n + 1];
        float v = (r & 1) ? (pre * bi + pim * br) : (pre * br - pim * bi);
        u16 hv, lv; split_bf(v, hv, lv);
        u32 off = (u32)(r * SB64 + j * 2);
        *(u16*)(smem + OFF_WH + off) = hv;
        *(u16*)(smem + OFF_WL + off) = lv;
    }
    __syncthreads();

    // ---- G1: S_raw[128r x 128col] = W * U^T, split-bf16 (3 products) ----
    {
        const int wm = wid & 1, wn = wid >> 1;
        float acc[4][4][4];
        #pragma unroll
        for (int mt = 0; mt < 4; ++mt)
            #pragma unroll
            for (int nt = 0; nt < 4; ++nt)
                #pragma unroll
                for (int r = 0; r < 4; ++r) acc[mt][nt][r] = 0.0f;

        #pragma unroll 1
        for (int prod = 0; prod < 3; ++prod) {
            u32 abase = sbase + ((prod == 2) ? OFF_WL : OFF_WH);
            u32 bbase = sbase + ((prod == 1) ? OFF_UL : OFF_UH);
            #pragma unroll
            for (int kt = 0; kt < 4; ++kt) {
                const int kb = kt * 32;
                u32 af[4][4], bf[4][2];
                #pragma unroll
                for (int mt = 0; mt < 4; ++mt) {
                    int row0 = wm * 64 + mt * 16;
                    u32 ad = abase + (u32)((row0 + (lane & 15)) * SB64 + kb + (lane >> 4) * 16);
                    ldsm_x4(ad, af[mt][0], af[mt][1], af[mt][2], af[mt][3]);
                }
                #pragma unroll
                for (int nt = 0; nt < 4; ++nt) {
                    int n0 = wn * 32 + nt * 8;
                    u32 bd = bbase + (u32)((n0 + (lane & 7)) * SB64 + kb + ((lane >> 3) & 1) * 16);
                    ldsm_x2(bd, bf[nt][0], bf[nt][1]);
                }
                #pragma unroll
                for (int mt = 0; mt < 4; ++mt)
                    #pragma unroll
                    for (int nt = 0; nt < 4; ++nt)
                        mma16816(acc[mt][nt], af[mt][0], af[mt][1], af[mt][2], af[mt][3],
                                 bf[nt][0], bf[nt][1]);
            }
        }
        __syncthreads();   // W dead; R overlays it
        float* R = (float*)(smem + OFF_R);
        #pragma unroll
        for (int mt = 0; mt < 4; ++mt)
            #pragma unroll
            for (int nt = 0; nt < 4; ++nt)
                #pragma unroll
                for (int rg = 0; rg < 4; ++rg) {
                    int r = wm * 64 + mt * 16 + (lane >> 2) + ((rg >= 2) ? 8 : 0);
                    int col = wn * 32 + nt * 8 + (lane & 3) * 2 + (rg & 1);
                    R[col * RSTR + r] = acc[mt][nt][rg];
                }
    }
    __syncthreads();

    // ---- Phase F: 32-chunk state scan; write St (h/l) [col][r] ----
    {
        const int n = tid & 63, b = tid >> 6;
        const float ar = aq[2 * n], ai = aq[2 * n + 1];
        const float* R = (const float*)(smem + OFF_R);
        float sre = 0.0f, sim = 0.0f;
        #pragma unroll 1
        for (int c = 0; c < NCH; ++c) {
            const int col = b * 32 + c;
            float2 v = *(const float2*)&R[col * RSTR + 2 * n];
            u16 h0, l0, h1, l1;
            split_bf(sre, h0, l0);
            split_bf(sim, h1, l1);
            u32 off = (u32)(col * SB128 + 4 * n);
            *(u32*)(smem + OFF_STH + off) = (u32)h0 | ((u32)h1 << 16);
            *(u32*)(smem + OFF_STL + off) = (u32)l0 | ((u32)l1 << 16);
            float nre = ar * sre - ai * sim + v.x;
            float nim = ar * sim + ai * sre + v.y;
            sre = nre; sim = nim;
        }
    }
    __syncthreads();   // R dead; T/V overlay it

    // ---- Phase C2: build T (h/l) and V (h/l) ----
    for (int idx = tid; idx < 64 * 64; idx += NTHREADS) {
        int i = idx >> 6, j = idx & 63;
        float v = (i >= j) ? kl[i - j] : 0.0f;
        u16 hv, lv; split_bf(v, hv, lv);
        u32 off = (u32)(i * SB64 + j * 2);
        *(u16*)(smem + OFF_TH + off) = hv;
        *(u16*)(smem + OFF_TL + off) = lv;
    }
    for (int idx = tid; idx < 64 * 128; idx += NTHREADS) {
        int i = idx >> 7, r = idx & 127, n = r >> 1;
        float pre = P[(i + 1) * PSTR + 2 * n];
        float pim = P[(i + 1) * PSTR + 2 * n + 1];
        float cr = ccs[2 * n], ci = ccs[2 * n + 1];
        float v = (r & 1) ? -(cr * pim + ci * pre) : (cr * pre - ci * pim);
        u16 hv, lv; split_bf(v, hv, lv);
        u32 off = (u32)(i * SB128 + r * 2);
        *(u16*)(smem + OFF_VH + off) = hv;
        *(u16*)(smem + OFF_VL + off) = lv;
    }
    __syncthreads();

    // ---- G2: Y[64 x 128] = T*U^T (K64) + V*St^T (K128), split-bf16 ----
    {
        const int wm = wid & 1, wn = wid >> 1;
        float acc[2][4][4];
        #pragma unroll
        for (int mt = 0; mt < 2; ++mt)
            #pragma unroll
            for (int nt = 0; nt < 4; ++nt)
                #pragma unroll
                for (int r = 0; r < 4; ++r) acc[mt][nt][r] = 0.0f;

        #pragma unroll 1
        for (int prod = 0; prod < 3; ++prod) {
            u32 abase = sbase + ((prod == 2) ? OFF_TL : OFF_TH);
            u32 bbase = sbase + ((prod == 1) ? OFF_UL : OFF_UH);
            #pragma unroll
            for (int kt = 0; kt < 4; ++kt) {
                const int kb = kt * 32;
                u32 af[2][4], bf[4][2];
                #pragma unroll
                for (int mt = 0; mt < 2; ++mt) {
                    int row0 = wm * 32 + mt * 16;
                    u32 ad = abase + (u32)((row0 + (lane & 15)) * SB64 + kb + (lane >> 4) * 16);
                    ldsm_x4(ad, af[mt][0], af[mt][1], af[mt][2], af[mt][3]);
                }
                #pragma unroll
                for (int nt = 0; nt < 4; ++nt) {
                    int n0 = wn * 32 + nt * 8;
                    u32 bd = bbase + (u32)((n0 + (lane & 7)) * SB64 + kb + ((lane >> 3) & 1) * 16);
                    ldsm_x2(bd, bf[nt][0], bf[nt][1]);
                }
                #pragma unroll
                for (int mt = 0; mt < 2; ++mt)
                    #pragma unroll
                    for (int nt = 0; nt < 4; ++nt)
                        mma16816(acc[mt][nt], af[mt][0], af[mt][1], af[mt][2], af[mt][3],
                                 bf[nt][0], bf[nt][1]);
            }
        }
        #pragma unroll 1
        for (int prod = 0; prod < 3; ++prod) {
            u32 abase = sbase + ((prod == 2) ? OFF_VL : OFF_VH);
            u32 bbase = sbase + ((prod == 1) ? OFF_STL : OFF_STH);
            #pragma unroll 1
            for (int kt = 0; kt < 8; ++kt) {
                const int kb = kt * 32;
                u32 af[2][4], bf[4][2];
                #pragma unroll
                for (int mt = 0; mt < 2; ++mt) {
                    int row0 = wm * 32 + mt * 16;
                    u32 ad = abase + (u32)((row0 + (lane & 15)) * SB128 + kb + (lane >> 4) * 16);
                    ldsm_x4(ad, af[mt][0], af[mt][1], af[mt][2], af[mt][3]);
                }
                #pragma unroll
                for (int nt = 0; nt < 4; ++nt) {
                    int n0 = wn * 32 + nt * 8;
                    u32 bd = bbase + (u32)((n0 + (lane & 7)) * SB128 + kb + ((lane >> 3) & 1) * 16);
                    ldsm_x2(bd, bf[nt][0], bf[nt][1]);
                }
                #pragma unroll
                for (int mt = 0; mt < 2; ++mt)
                    #pragma unroll
                    for (int nt = 0; nt < 4; ++nt)
                        mma16816(acc[mt][nt], af[mt][0], af[mt][1], af[mt][2], af[mt][3],
                                 bf[nt][0], bf[nt][1]);
            }
        }

        // ---- Epilogue: y = Y + D*u, direct from fragments ----
        const float Dh = Dv[h];
        #pragma unroll
        for (int mt = 0; mt < 2; ++mt)
            #pragma unroll
            for (int nt = 0; nt < 4; ++nt)
                #pragma unroll
                for (int rg = 0; rg < 4; ++rg) {
                    int i = wm * 32 + mt * 16 + (lane >> 2) + ((rg >= 2) ? 8 : 0);
                    int col = wn * 32 + nt * 8 + (lane & 3) * 2 + (rg & 1);
                    int b = col >> 5, c = col & 31;
                    size_t a = ((size_t)b * HH + h) * (size_t)LSEQ + (size_t)(c * 64 + i);
                    y[a] = acc[mt][nt][rg] + Dh * __ldg(&u[a]);
                }
    }
}

extern "C" void kernel_launch(void* const* d_in, const int* in_sizes, int n_in,
                              void* d_out, int out_size) {
    const float* u    = (const float*)d_in[0];
    const float* lnr  = (const float*)d_in[1];
    const float* im   = (const float*)d_in[2];
    const float* B_re = (const float*)d_in[3];
    const float* B_im = (const float*)d_in[4];
    const float* C_re = (const float*)d_in[5];
    const float* C_im = (const float*)d_in[6];
    const float* ldt  = (const float*)d_in[7];
    const float* Dv   = (const float*)d_in[8];
    float* y = (float*)d_out;

    static int attr_done = 0;
    if (!attr_done) {
        cudaFuncSetAttribute(ssm_mma_kernel,
                             cudaFuncAttributeMaxDynamicSharedMemorySize, SMEM_BYTES);
        attr_done = 1;
    }

    setup_kernel<<<(HH * NN + 255) / 256, 256>>>(lnr, im, B_re, B_im, C_re, C_im, ldt);
    ssm_mma_kernel<<<NBLK, NTHREADS, SMEM_BYTES>>>(u, Dv, y);
}

// round 7
// speedup vs baseline: 1.9021x; 1.0532x over previous
#include <cuda_runtime.h>
#include <cuda_bf16.h>
#include <cstdint>

#define HH 768
#define NN 64
#define LSEQ 2048
#define BB 4
#define Q 64
#define NCH 32
#define NTHREADS 512
#define NBLK HH

typedef unsigned int u32;
typedef unsigned short u16;

// ---------------- smem layout (bytes) ----------------
#define SB64 144
#define SB128 272
#define OFF_AQ   0            // 128 f32
#define OFF_KL   512          // 64 f32
#define OFF_BBS  768          // 128 f32
#define OFF_CCS  1280         // 128 f32
#define OFF_KMS  1792         // 128 f32
#define OFF_UH   4096                      // 128 x 144 = 18432
#define OFF_UL   (OFF_UH + 18432)
#define OFF_STH  (OFF_UL + 18432)          // 128 x 272 = 34816
#define OFF_STL  (OFF_STH + 34816)
#define OFF_P    (OFF_STL + 34816)         // fp32 powers 65 x 130 f
#define PSTR     130
#define OFF_X    (OFF_P + 33824)           // union region
#define OFF_WH   (OFF_X)
#define OFF_WL   (OFF_X + 18432)
#define OFF_R    (OFF_X)
#define RSTR     132
#define OFF_TH   (OFF_X)
#define OFF_TL   (OFF_X + 9216)
#define OFF_VH   (OFF_X + 18432)
#define OFF_VL   (OFF_X + 35840)
#define SMEM_BYTES (OFF_X + 67584)         // 212000

// ---------------- helpers ----------------
__device__ __forceinline__ u32 smem_u32(const void* p) {
    u32 a;
    asm("{ .reg .u64 t; cvta.to.shared.u64 t, %1; cvt.u32.u64 %0, t; }" : "=r"(a) : "l"(p));
    return a;
}
__device__ __forceinline__ void ldsm_x4(u32 addr, u32& r0, u32& r1, u32& r2, u32& r3) {
    asm volatile("ldmatrix.sync.aligned.m8n8.x4.shared.b16 {%0,%1,%2,%3}, [%4];"
                 : "=r"(r0), "=r"(r1), "=r"(r2), "=r"(r3) : "r"(addr));
}
__device__ __forceinline__ void ldsm_x2(u32 addr, u32& r0, u32& r1) {
    asm volatile("ldmatrix.sync.aligned.m8n8.x2.shared.b16 {%0,%1}, [%2];"
                 : "=r"(r0), "=r"(r1) : "r"(addr));
}
__device__ __forceinline__ void mma16816(float* d, u32 a0, u32 a1, u32 a2, u32 a3,
                                         u32 b0, u32 b1) {
    asm volatile("mma.sync.aligned.m16n8k16.row.col.f32.bf16.bf16.f32 "
                 "{%0,%1,%2,%3}, {%4,%5,%6,%7}, {%8,%9}, {%0,%1,%2,%3};"
                 : "+f"(d[0]), "+f"(d[1]), "+f"(d[2]), "+f"(d[3])
                 : "r"(a0), "r"(a1), "r"(a2), "r"(a3), "r"(b0), "r"(b1));
}
__device__ __forceinline__ void split_bf(float v, u16& h, u16& l) {
    __nv_bfloat16 bh = __float2bfloat16(v);
    float rem = v - __bfloat162float(bh);
    __nv_bfloat16 bl = __float2bfloat16(rem);
    h = __bfloat16_as_ushort(bh);
    l = __bfloat16_as_ushort(bl);
}

// Per-(h,n) discretized params
__device__ float2 g_A[HH * NN];
__device__ float2 g_Bb[HH * NN];
__device__ float2 g_C[HH * NN];
__device__ float2 g_K[HH * NN];

// ---------------- Kernel 0: ZOH discretization ----------------
__global__ void setup_kernel(const float* __restrict__ log_neg_real,
                             const float* __restrict__ imag,
                             const float* __restrict__ B_re,
                             const float* __restrict__ B_im,
                             const float* __restrict__ C_re,
                             const float* __restrict__ C_im,
                             const float* __restrict__ log_dt) {
    int idx = blockIdx.x * blockDim.x + threadIdx.x;
    if (idx >= HH * NN) return;
    int h = idx >> 6;

    float lre = -expf(log_neg_real[idx]);
    float lim = imag[idx];
    float dt  = expf(log_dt[h]);

    float zre = lre * dt, zim = lim * dt;
    float ea = expf(zre);
    float sn, cs; sincosf(zim, &sn, &cs);
    float Are = ea * cs, Aim = ea * sn;

    float dre = Are - 1.0f, dim = Aim;
    float den = lre * lre + lim * lim;
    float ire = lre / den, iim = -lim / den;
    float tre = dre * ire - dim * iim;
    float tim = dre * iim + dim * ire;
    float br = B_re[idx], bi = B_im[idx];
    float Bbre = tre * br - tim * bi;
    float Bbim = tre * bi + tim * br;

    float cr = C_re[idx], ci = C_im[idx];

    g_A[idx]  = make_float2(Are, Aim);
    g_Bb[idx] = make_float2(Bbre, Bbim);
    g_C[idx]  = make_float2(cr, ci);
    g_K[idx]  = make_float2(cr * Bbre - ci * Bbim, cr * Bbim + ci * Bbre);
}

// ---------------- Kernel 1: chunked SSM on HMMA, 512 threads ----------------
__global__ void __launch_bounds__(NTHREADS)
ssm_mma_kernel(const float* __restrict__ u,
               const float* __restrict__ Dv,
               float* __restrict__ y) {
    extern __shared__ char smem[];
    const u32 sbase = smem_u32(smem);
    const int tid = threadIdx.x;
    const int wid = tid >> 5;
    const int lane = tid & 31;
    const int h = blockIdx.x;

    float* aq  = (float*)(smem + OFF_AQ);
    float* kl  = (float*)(smem + OFF_KL);
    float* bbs = (float*)(smem + OFF_BBS);
    float* ccs = (float*)(smem + OFF_CCS);
    float* kms = (float*)(smem + OFF_KMS);
    float* P   = (float*)(smem + OFF_P);

    // ---- Phase A0: params + P[0], P[1]; Phase D: load+split u (concurrent) ----
    if (tid < NN) {
        const int n = tid;
        float2 a  = g_A[h * NN + n];
        float2 bb = g_Bb[h * NN + n];
        float2 cc = g_C[h * NN + n];
        float2 kk = g_K[h * NN + n];
        bbs[2 * n] = bb.x; bbs[2 * n + 1] = bb.y;
        ccs[2 * n] = cc.x; ccs[2 * n + 1] = cc.y;
        kms[2 * n] = kk.x; kms[2 * n + 1] = kk.y;
        P[0 * PSTR + 2 * n] = 1.0f; P[0 * PSTR + 2 * n + 1] = 0.0f;
        P[1 * PSTR + 2 * n] = a.x;  P[1 * PSTR + 2 * n + 1] = a.y;
    }
    {
        const float4* u4 = (const float4*)u;
        for (int idx = tid; idx < 2048; idx += NTHREADS) {
            int b = idx >> 9, l4 = idx & 511;
            float4 v = u4[((size_t)b * HH + h) * 512 + (u32)l4];
            int c = (l4 >> 4) & 31, j = (l4 & 15) * 4;
            int col = b * 32 + c;
            u16 hs[4], ls[4];
            split_bf(v.x, hs[0], ls[0]);
            split_bf(v.y, hs[1], ls[1]);
            split_bf(v.z, hs[2], ls[2]);
            split_bf(v.w, hs[3], ls[3]);
            u32 off = (u32)(col * SB64 + j * 2);
            *(uint2*)(smem + OFF_UH + off) = make_uint2((u32)hs[0] | ((u32)hs[1] << 16),
                                                        (u32)hs[2] | ((u32)hs[3] << 16));
            *(uint2*)(smem + OFF_UL + off) = make_uint2((u32)ls[0] | ((u32)ls[1] << 16),
                                                        (u32)ls[2] | ((u32)ls[3] << 16));
        }
    }
    __syncthreads();

    // ---- Phase A1: log-doubling powers P[l] = P[m] * P[l-m] ----
    #pragma unroll 1
    for (int m = 1; m < Q; m <<= 1) {
        int cnt = (m < Q - m) ? m : (Q - m);      // entries l = m+1 .. m+cnt
        for (int idx = tid; idx < cnt * 64; idx += NTHREADS) {
            int dl = idx >> 6, n = idx & 63;
            int l = m + 1 + dl;
            float are = P[m * PSTR + 2 * n],       aim = P[m * PSTR + 2 * n + 1];
            float bre = P[(l - m) * PSTR + 2 * n], bim = P[(l - m) * PSTR + 2 * n + 1];
            P[l * PSTR + 2 * n]     = are * bre - aim * bim;
            P[l * PSTR + 2 * n + 1] = are * bim + aim * bre;
        }
        __syncthreads();
    }

    // ---- Phase B: kl[l] = Re(sum K A^l) (8 lanes per l); aq = A^Q ----
    {
        const int l = tid >> 3, part = tid & 7;
        float acc = 0.0f;
        #pragma unroll
        for (int k = 0; k < 8; ++k) {
            int n = part * 8 + k;
            acc += kms[2 * n] * P[l * PSTR + 2 * n]
                 - kms[2 * n + 1] * P[l * PSTR + 2 * n + 1];
        }
        acc += __shfl_down_sync(0xFFFFFFFFu, acc, 4, 8);
        acc += __shfl_down_sync(0xFFFFFFFFu, acc, 2, 8);
        acc += __shfl_down_sync(0xFFFFFFFFu, acc, 1, 8);
        if (part == 0) kl[l] = acc;
        if (tid < 128) aq[tid] = P[Q * PSTR + tid];
    }
    // ---- Phase C1: build W (h/l) ----
    __syncthreads();
    for (int idx = tid; idx < 128 * 64; idx += NTHREADS) {
        int r = idx >> 6, j = idx & 63, n = r >> 1;
        float pre = P[(Q - 1 - j) * PSTR + 2 * n];
        float pim = P[(Q - 1 - j) * PSTR + 2 * n + 1];
        float br = bbs[2 * n], bi = bbs[2 * n + 1];
        float v = (r & 1) ? (pre * bi + pim * br) : (pre * br - pim * bi);
        u16 hv, lv; split_bf(v, hv, lv);
        u32 off = (u32)(r * SB64 + j * 2);
        *(u16*)(smem + OFF_WH + off) = hv;
        *(u16*)(smem + OFF_WL + off) = lv;
    }
    __syncthreads();

    // ---- G1: S_raw[128 x 128] = W * U^T, 16 warps, 32x32 tiles ----
    {
        const int wm = wid & 3, wn = wid >> 2;
        float acc[2][4][4];
        #pragma unroll
        for (int mt = 0; mt < 2; ++mt)
            #pragma unroll
            for (int nt = 0; nt < 4; ++nt)
                #pragma unroll
                for (int r = 0; r < 4; ++r) acc[mt][nt][r] = 0.0f;

        #pragma unroll 1
        for (int prod = 0; prod < 3; ++prod) {
            u32 abase = sbase + ((prod == 2) ? OFF_WL : OFF_WH);
            u32 bbase = sbase + ((prod == 1) ? OFF_UL : OFF_UH);
            #pragma unroll
            for (int kt = 0; kt < 4; ++kt) {
                const int kb = kt * 32;
                u32 af[2][4], bf[4][2];
                #pragma unroll
                for (int mt = 0; mt < 2; ++mt) {
                    int row0 = wm * 32 + mt * 16;
                    u32 ad = abase + (u32)((row0 + (lane & 15)) * SB64 + kb + (lane >> 4) * 16);
                    ldsm_x4(ad, af[mt][0], af[mt][1], af[mt][2], af[mt][3]);
                }
                #pragma unroll
                for (int nt = 0; nt < 4; ++nt) {
                    int n0 = wn * 32 + nt * 8;
                    u32 bd = bbase + (u32)((n0 + (lane & 7)) * SB64 + kb + ((lane >> 3) & 1) * 16);
                    ldsm_x2(bd, bf[nt][0], bf[nt][1]);
                }
                #pragma unroll
                for (int mt = 0; mt < 2; ++mt)
                    #pragma unroll
                    for (int nt = 0; nt < 4; ++nt)
                        mma16816(acc[mt][nt], af[mt][0], af[mt][1], af[mt][2], af[mt][3],
                                 bf[nt][0], bf[nt][1]);
            }
        }
        __syncthreads();   // W dead; R overlays it
        float* R = (float*)(smem + OFF_R);
        #pragma unroll
        for (int mt = 0; mt < 2; ++mt)
            #pragma unroll
            for (int nt = 0; nt < 4; ++nt)
                #pragma unroll
                for (int rg = 0; rg < 4; ++rg) {
                    int r = wm * 32 + mt * 16 + (lane >> 2) + ((rg >= 2) ? 8 : 0);
                    int col = wn * 32 + nt * 8 + (lane & 3) * 2 + (rg & 1);
                    R[col * RSTR + r] = acc[mt][nt][rg];
                }
    }
    __syncthreads();

    // ---- Phase F: 32-chunk state scan (256 threads); write St (h/l) ----
    if (tid < 256) {
        const int n = tid & 63, b = tid >> 6;
        const float ar = aq[2 * n], ai = aq[2 * n + 1];
        const float* R = (const float*)(smem + OFF_R);
        float sre = 0.0f, sim = 0.0f;
        #pragma unroll 1
        for (int c = 0; c < NCH; ++c) {
            const int col = b * 32 + c;
            float2 v = *(const float2*)&R[col * RSTR + 2 * n];
            u16 h0, l0, h1, l1;
            split_bf(sre, h0, l0);
            split_bf(sim, h1, l1);
            u32 off = (u32)(col * SB128 + 4 * n);
            *(u32*)(smem + OFF_STH + off) = (u32)h0 | ((u32)h1 << 16);
            *(u32*)(smem + OFF_STL + off) = (u32)l0 | ((u32)l1 << 16);
            float nre = ar * sre - ai * sim + v.x;
            float nim = ar * sim + ai * sre + v.y;
            sre = nre; sim = nim;
        }
    }
    __syncthreads();   // R dead; T/V overlay it

    // ---- Phase C2: build T (h/l) and V (h/l) ----
    for (int idx = tid; idx < 64 * 64; idx += NTHREADS) {
        int i = idx >> 6, j = idx & 63;
        float v = (i >= j) ? kl[i - j] : 0.0f;
        u16 hv, lv; split_bf(v, hv, lv);
        u32 off = (u32)(i * SB64 + j * 2);
        *(u16*)(smem + OFF_TH + off) = hv;
        *(u16*)(smem + OFF_TL + off) = lv;
    }
    for (int idx = tid; idx < 64 * 128; idx += NTHREADS) {
        int i = idx >> 7, r = idx & 127, n = r >> 1;
        float pre = P[(i + 1) * PSTR + 2 * n];
        float pim = P[(i + 1) * PSTR + 2 * n + 1];
        float cr = ccs[2 * n], ci = ccs[2 * n + 1];
        float v = (r & 1) ? -(cr * pim + ci * pre) : (cr * pre - ci * pim);
        u16 hv, lv; split_bf(v, hv, lv);
        u32 off = (u32)(i * SB128 + r * 2);
        *(u16*)(smem + OFF_VH + off) = hv;
        *(u16*)(smem + OFF_VL + off) = lv;
    }
    __syncthreads();

    // ---- G2: Y[64 x 128] = T*U^T (K64) + V*St^T (K128), 16 warps, 16x32 tiles ----
    {
        const int wm = wid & 3, wn = wid >> 2;
        float acc[4][4];
        #pragma unroll
        for (int nt = 0; nt < 4; ++nt)
            #pragma unroll
            for (int r = 0; r < 4; ++r) acc[nt][r] = 0.0f;

        #pragma unroll 1
        for (int prod = 0; prod < 3; ++prod) {
            u32 abase = sbase + ((prod == 2) ? OFF_TL : OFF_TH);
            u32 bbase = sbase + ((prod == 1) ? OFF_UL : OFF_UH);
            #pragma unroll
            for (int kt = 0; kt < 4; ++kt) {
                const int kb = kt * 32;
                u32 af[4], bf[4][2];
                {
                    int row0 = wm * 16;
                    u32 ad = abase + (u32)((row0 + (lane & 15)) * SB64 + kb + (lane >> 4) * 16);
                    ldsm_x4(ad, af[0], af[1], af[2], af[3]);
                }
                #pragma unroll
                for (int nt = 0; nt < 4; ++nt) {
                    int n0 = wn * 32 + nt * 8;
                    u32 bd = bbase + (u32)((n0 + (lane & 7)) * SB64 + kb + ((lane >> 3) & 1) * 16);
                    ldsm_x2(bd, bf[nt][0], bf[nt][1]);
                }
                #pragma unroll
                for (int nt = 0; nt < 4; ++nt)
                    mma16816(acc[nt], af[0], af[1], af[2], af[3], bf[nt][0], bf[nt][1]);
            }
        }
        #pragma unroll 1
        for (int prod = 0; prod < 3; ++prod) {
            u32 abase = sbase + ((prod == 2) ? OFF_VL : OFF_VH);
            u32 bbase = sbase + ((prod == 1) ? OFF_STL : OFF_STH);
            #pragma unroll 1
            for (int kt = 0; kt < 8; ++kt) {
                const int kb = kt * 32;
                u32 af[4], bf[4][2];
                {
                    int row0 = wm * 16;
                    u32 ad = abase + (u32)((row0 + (lane & 15)) * SB128 + kb + (lane >> 4) * 16);
                    ldsm_x4(ad, af[0], af[1], af[2], af[3]);
                }
                #pragma unroll
                for (int nt = 0; nt < 4; ++nt) {
                    int n0 = wn * 32 + nt * 8;
                    u32 bd = bbase + (u32)((n0 + (lane & 7)) * SB128 + kb + ((lane >> 3) & 1) * 16);
                    ldsm_x2(bd, bf[nt][0], bf[nt][1]);
                }
                #pragma unroll
                for (int nt = 0; nt < 4; ++nt)
                    mma16816(acc[nt], af[0], af[1], af[2], af[3], bf[nt][0], bf[nt][1]);
            }
        }

        // ---- Epilogue: y = Y + D*u, direct from fragments ----
        const float Dh = Dv[h];
        #pragma unroll
        for (int nt = 0; nt < 4; ++nt)
            #pragma unroll
            for (int rg = 0; rg < 4; ++rg) {
                int i = wm * 16 + (lane >> 2) + ((rg >= 2) ? 8 : 0);
                int col = wn * 32 + nt * 8 + (lane & 3) * 2 + (rg & 1);
                int b = col >> 5, c = col & 31;
                size_t a = ((size_t)b * HH + h) * (size_t)LSEQ + (size_t)(c * 64 + i);
                y[a] = acc[nt][rg] + Dh * __ldg(&u[a]);
            }
    }
}

extern "C" void kernel_launch(void* const* d_in, const int* in_sizes, int n_in,
                              void* d_out, int out_size) {
    const float* u    = (const float*)d_in[0];
    const float* lnr  = (const float*)d_in[1];
    const float* im   = (const float*)d_in[2];
    const float* B_re = (const float*)d_in[3];
    const float* B_im = (const float*)d_in[4];
    const float* C_re = (const float*)d_in[5];
    const float* C_im = (const float*)d_in[6];
    const float* ldt  = (const float*)d_in[7];
    const float* Dv   = (const float*)d_in[8];
    float* y = (float*)d_out;

    static int attr_done = 0;
    if (!attr_done) {
        cudaFuncSetAttribute(ssm_mma_kernel,
                             cudaFuncAttributeMaxDynamicSharedMemorySize, SMEM_BYTES);
        attr_done = 1;
    }

    setup_kernel<<<(HH * NN + 255) / 256, 256>>>(lnr, im, B_re, B_im, C_re, C_im, ldt);
    ssm_mma_kernel<<<NBLK, NTHREADS, SMEM_BYTES>>>(u, Dv, y);
}

// round 8
// speedup vs baseline: 2.0097x; 1.0566x over previous
#include <cuda_runtime.h>
#include <cuda_bf16.h>
#include <cstdint>

#define HH 768
#define NN 64
#define LSEQ 2048
#define BB 4
#define Q 64
#define NCH 32
#define NTHREADS 512
#define NBLK HH

typedef unsigned int u32;
typedef unsigned short u16;

// ---------------- smem layout (bytes) ----------------
#define SB64 144
#define SB128 272
#define OFF_AQ   0            // 128 f32
#define OFF_KL   512          // 64 f32
#define OFF_BBS  768          // 128 f32
#define OFF_CCS  1280         // 128 f32
#define OFF_KMS  1792         // 128 f32
#define OFF_UH   4096                      // 128 x 144 = 18432
#define OFF_UL   (OFF_UH + 18432)
#define OFF_STH  (OFF_UL + 18432)          // 128 x 272 = 34816
#define OFF_STL  (OFF_STH + 34816)
#define OFF_P    (OFF_STL + 34816)         // fp32 powers 65 x 130 f
#define PSTR     130
#define OFF_X    (OFF_P + 33824)           // union region
#define OFF_WH   (OFF_X)
#define OFF_WL   (OFF_X + 18432)
#define OFF_R    (OFF_X)
#define RSTR     132
#define OFF_TH   (OFF_X)
#define OFF_TL   (OFF_X + 9216)
#define OFF_VH   (OFF_X + 18432)
#define OFF_VL   (OFF_X + 35840)
#define SMEM_BYTES (OFF_X + 67584)         // 212000
// Y staging overlays U panels after G2 (fp32, [col][i] stride 68 floats)
#define OFF_Y    OFF_UH
#define YSTR     68

// ---------------- helpers ----------------
__device__ __forceinline__ u32 smem_u32(const void* p) {
    u32 a;
    asm("{ .reg .u64 t; cvta.to.shared.u64 t, %1; cvt.u32.u64 %0, t; }" : "=r"(a) : "l"(p));
    return a;
}
__device__ __forceinline__ void ldsm_x4(u32 addr, u32& r0, u32& r1, u32& r2, u32& r3) {
    asm volatile("ldmatrix.sync.aligned.m8n8.x4.shared.b16 {%0,%1,%2,%3}, [%4];"
                 : "=r"(r0), "=r"(r1), "=r"(r2), "=r"(r3) : "r"(addr));
}
__device__ __forceinline__ void mma16816(float* d, u32 a0, u32 a1, u32 a2, u32 a3,
                                         u32 b0, u32 b1) {
    asm volatile("mma.sync.aligned.m16n8k16.row.col.f32.bf16.bf16.f32 "
                 "{%0,%1,%2,%3}, {%4,%5,%6,%7}, {%8,%9}, {%0,%1,%2,%3};"
                 : "+f"(d[0]), "+f"(d[1]), "+f"(d[2]), "+f"(d[3])
                 : "r"(a0), "r"(a1), "r"(a2), "r"(a3), "r"(b0), "r"(b1));
}
__device__ __forceinline__ void split_bf(float v, u16& h, u16& l) {
    __nv_bfloat16 bh = __float2bfloat16(v);
    float rem = v - __bfloat162float(bh);
    __nv_bfloat16 bl = __float2bfloat16(rem);
    h = __bfloat16_as_ushort(bh);
    l = __bfloat16_as_ushort(bl);
}

// Per-(h,n) discretized params
__device__ float2 g_A[HH * NN];
__device__ float2 g_Bb[HH * NN];
__device__ float2 g_C[HH * NN];
__device__ float2 g_K[HH * NN];

// ---------------- Kernel 0: ZOH discretization ----------------
__global__ void setup_kernel(const float* __restrict__ log_neg_real,
                             const float* __restrict__ imag,
                             const float* __restrict__ B_re,
                             const float* __restrict__ B_im,
                             const float* __restrict__ C_re,
                             const float* __restrict__ C_im,
                             const float* __restrict__ log_dt) {
    int idx = blockIdx.x * blockDim.x + threadIdx.x;
    if (idx >= HH * NN) return;
    int h = idx >> 6;

    float lre = -expf(log_neg_real[idx]);
    float lim = imag[idx];
    float dt  = expf(log_dt[h]);

    float zre = lre * dt, zim = lim * dt;
    float ea = expf(zre);
    float sn, cs; sincosf(zim, &sn, &cs);
    float Are = ea * cs, Aim = ea * sn;

    float dre = Are - 1.0f, dim = Aim;
    float den = lre * lre + lim * lim;
    float ire = lre / den, iim = -lim / den;
    float tre = dre * ire - dim * iim;
    float tim = dre * iim + dim * ire;
    float br = B_re[idx], bi = B_im[idx];
    float Bbre = tre * br - tim * bi;
    float Bbim = tre * bi + tim * br;

    float cr = C_re[idx], ci = C_im[idx];

    g_A[idx]  = make_float2(Are, Aim);
    g_Bb[idx] = make_float2(Bbre, Bbim);
    g_C[idx]  = make_float2(cr, ci);
    g_K[idx]  = make_float2(cr * Bbre - ci * Bbim, cr * Bbim + ci * Bbre);
}

// ---------------- Kernel 1: chunked SSM on HMMA, 512 threads ----------------
__global__ void __launch_bounds__(NTHREADS)
ssm_mma_kernel(const float* __restrict__ u,
               const float* __restrict__ Dv,
               float* __restrict__ y) {
    extern __shared__ char smem[];
    const u32 sbase = smem_u32(smem);
    const int tid = threadIdx.x;
    const int wid = tid >> 5;
    const int lane = tid & 31;
    const int h = blockIdx.x;

    float* aq  = (float*)(smem + OFF_AQ);
    float* kl  = (float*)(smem + OFF_KL);
    float* bbs = (float*)(smem + OFF_BBS);
    float* ccs = (float*)(smem + OFF_CCS);
    float* kms = (float*)(smem + OFF_KMS);
    float* P   = (float*)(smem + OFF_P);

    // ---- Phase A0: params + serial powers P[0..8]; Phase D: load+split u ----
    if (tid < NN) {
        const int n = tid;
        float2 a  = g_A[h * NN + n];
        float2 bb = g_Bb[h * NN + n];
        float2 cc = g_C[h * NN + n];
        float2 kk = g_K[h * NN + n];
        bbs[2 * n] = bb.x; bbs[2 * n + 1] = bb.y;
        ccs[2 * n] = cc.x; ccs[2 * n + 1] = cc.y;
        kms[2 * n] = kk.x; kms[2 * n + 1] = kk.y;
        ((float2*)&P[0 * PSTR])[n] = make_float2(1.0f, 0.0f);
        ((float2*)&P[1 * PSTR])[n] = a;
        float pre = a.x, pim = a.y;
        #pragma unroll
        for (int l = 2; l <= 8; ++l) {
            float nre = pre * a.x - pim * a.y;
            float nim = pre * a.y + pim * a.x;
            pre = nre; pim = nim;
            ((float2*)&P[l * PSTR])[n] = make_float2(pre, pim);
        }
    }
    {
        const float4* u4 = (const float4*)u;
        for (int idx = tid; idx < 2048; idx += NTHREADS) {
            int b = idx >> 9, l4 = idx & 511;
            float4 v = u4[((size_t)b * HH + h) * 512 + (u32)l4];
            int c = (l4 >> 4) & 31, j = (l4 & 15) * 4;
            int col = b * 32 + c;
            u16 hs[4], ls[4];
            split_bf(v.x, hs[0], ls[0]);
            split_bf(v.y, hs[1], ls[1]);
            split_bf(v.z, hs[2], ls[2]);
            split_bf(v.w, hs[3], ls[3]);
            u32 off = (u32)(col * SB64 + j * 2);
            *(uint2*)(smem + OFF_UH + off) = make_uint2((u32)hs[0] | ((u32)hs[1] << 16),
                                                        (u32)hs[2] | ((u32)hs[3] << 16));
            *(uint2*)(smem + OFF_UL + off) = make_uint2((u32)ls[0] | ((u32)ls[1] << 16),
                                                        (u32)ls[2] | ((u32)ls[3] << 16));
        }
    }
    __syncthreads();

    // ---- Phase A1: 3 doubling rounds: m = 8, 16, 32 ----
    #pragma unroll 1
    for (int m = 8; m < Q; m <<= 1) {
        for (int idx = tid; idx < m * 64; idx += NTHREADS) {
            int dl = idx >> 6, n = idx & 63;
            int l = m + 1 + dl;
            float2 am = ((const float2*)&P[m * PSTR])[n];
            float2 bm = ((const float2*)&P[(l - m) * PSTR])[n];
            ((float2*)&P[l * PSTR])[n] =
                make_float2(am.x * bm.x - am.y * bm.y, am.x * bm.y + am.y * bm.x);
        }
        __syncthreads();
    }

    // ---- Phase B: kl[l] = Re(sum K A^l) (8 lanes per l); aq = A^Q ----
    {
        const int l = tid >> 3, part = tid & 7;
        float acc = 0.0f;
        #pragma unroll
        for (int k = 0; k < 8; ++k) {
            int n = part * 8 + k;
            float2 pp = ((const float2*)&P[l * PSTR])[n];
            acc += kms[2 * n] * pp.x - kms[2 * n + 1] * pp.y;
        }
        acc += __shfl_down_sync(0xFFFFFFFFu, acc, 4, 8);
        acc += __shfl_down_sync(0xFFFFFFFFu, acc, 2, 8);
        acc += __shfl_down_sync(0xFFFFFFFFu, acc, 1, 8);
        if (part == 0) kl[l] = acc;
        if (tid < 128) aq[tid] = P[Q * PSTR + tid];
    }
    // ---- Phase C1: build W (h/l), 2 j per thread, u32 stores ----
    for (int idx = tid; idx < 128 * 32; idx += NTHREADS) {
        int r = idx >> 5, jp = idx & 31, n = r >> 1;
        int j0 = jp * 2;
        float2 p0 = ((const float2*)&P[(Q - 1 - j0) * PSTR])[n];
        float2 p1 = ((const float2*)&P[(Q - 2 - j0) * PSTR])[n];
        float br = bbs[2 * n], bi = bbs[2 * n + 1];
        float v0 = (r & 1) ? (p0.x * bi + p0.y * br) : (p0.x * br - p0.y * bi);
        float v1 = (r & 1) ? (p1.x * bi + p1.y * br) : (p1.x * br - p1.y * bi);
        u16 h0, l0, h1, l1;
        split_bf(v0, h0, l0);
        split_bf(v1, h1, l1);
        u32 off = (u32)(r * SB64 + j0 * 2);
        *(u32*)(smem + OFF_WH + off) = (u32)h0 | ((u32)h1 << 16);
        *(u32*)(smem + OFF_WL + off) = (u32)l0 | ((u32)l1 << 16);
    }
    __syncthreads();

    // ---- G1: S_raw[128 x 128] = W * U^T, 16 warps, 32x32 tiles ----
    {
        const int wm = wid & 3, wn = wid >> 2;
        float acc[2][4][4];
        #pragma unroll
        for (int mt = 0; mt < 2; ++mt)
            #pragma unroll
            for (int nt = 0; nt < 4; ++nt)
                #pragma unroll
                for (int r = 0; r < 4; ++r) acc[mt][nt][r] = 0.0f;

        #pragma unroll 1
        for (int prod = 0; prod < 3; ++prod) {
            u32 abase = sbase + ((prod == 2) ? OFF_WL : OFF_WH);
            u32 bbase = sbase + ((prod == 1) ? OFF_UL : OFF_UH);
            #pragma unroll
            for (int kt = 0; kt < 4; ++kt) {
                const int kb = kt * 32;
                u32 af[2][4], bf[4][2];
                #pragma unroll
                for (int mt = 0; mt < 2; ++mt) {
                    int row0 = wm * 32 + mt * 16;
                    u32 ad = abase + (u32)((row0 + (lane & 15)) * SB64 + kb + (lane >> 4) * 16);
                    ldsm_x4(ad, af[mt][0], af[mt][1], af[mt][2], af[mt][3]);
                }
                #pragma unroll
                for (int ntp = 0; ntp < 2; ++ntp) {
                    int n0 = wn * 32 + ntp * 16;
                    u32 bd = bbase + (u32)((n0 + ((lane >> 3) & 1) * 8 + (lane & 7)) * SB64
                                           + kb + (lane >> 4) * 16);
                    u32 q0, q1, q2, q3;
                    ldsm_x4(bd, q0, q1, q2, q3);
                    bf[2 * ntp][0] = q0; bf[2 * ntp][1] = q2;
                    bf[2 * ntp + 1][0] = q1; bf[2 * ntp + 1][1] = q3;
                }
                #pragma unroll
                for (int mt = 0; mt < 2; ++mt)
                    #pragma unroll
                    for (int nt = 0; nt < 4; ++nt)
                        mma16816(acc[mt][nt], af[mt][0], af[mt][1], af[mt][2], af[mt][3],
                                 bf[nt][0], bf[nt][1]);
            }
        }
        __syncthreads();   // W dead; R overlays it
        float* R = (float*)(smem + OFF_R);
        #pragma unroll
        for (int mt = 0; mt < 2; ++mt)
            #pragma unroll
            for (int nt = 0; nt < 4; ++nt)
                #pragma unroll
                for (int rg = 0; rg < 4; ++rg) {
                    int r = wm * 32 + mt * 16 + (lane >> 2) + ((rg >= 2) ? 8 : 0);
                    int col = wn * 32 + nt * 8 + (lane & 3) * 2 + (rg & 1);
                    R[col * RSTR + r] = acc[mt][nt][rg];
                }
    }
    __syncthreads();

    // ---- Phase F: 32-chunk state scan (256 threads); write St (h/l) ----
    if (tid < 256) {
        const int n = tid & 63, b = tid >> 6;
        const float ar = aq[2 * n], ai = aq[2 * n + 1];
        const float* R = (const float*)(smem + OFF_R);
        float sre = 0.0f, sim = 0.0f;
        #pragma unroll 1
        for (int c = 0; c < NCH; ++c) {
            const int col = b * 32 + c;
            float2 v = *(const float2*)&R[col * RSTR + 2 * n];
            u16 h0, l0, h1, l1;
            split_bf(sre, h0, l0);
            split_bf(sim, h1, l1);
            u32 off = (u32)(col * SB128 + 4 * n);
            *(u32*)(smem + OFF_STH + off) = (u32)h0 | ((u32)h1 << 16);
            *(u32*)(smem + OFF_STL + off) = (u32)l0 | ((u32)l1 << 16);
            float nre = ar * sre - ai * sim + v.x;
            float nim = ar * sim + ai * sre + v.y;
            sre = nre; sim = nim;
        }
    }
    __syncthreads();   // R dead; T/V overlay it

    // ---- Phase C2: build T (h/l) and V (h/l), vectorized ----
    for (int idx = tid; idx < 64 * 32; idx += NTHREADS) {
        int i = idx >> 5, jp = idx & 31;
        int j0 = jp * 2;
        float v0 = (i >= j0) ? kl[i - j0] : 0.0f;
        float v1 = (i >= j0 + 1) ? kl[i - j0 - 1] : 0.0f;
        u16 h0, l0, h1, l1;
        split_bf(v0, h0, l0);
        split_bf(v1, h1, l1);
        u32 off = (u32)(i * SB64 + j0 * 2);
        *(u32*)(smem + OFF_TH + off) = (u32)h0 | ((u32)h1 << 16);
        *(u32*)(smem + OFF_TL + off) = (u32)l0 | ((u32)l1 << 16);
    }
    for (int idx = tid; idx < 64 * 64; idx += NTHREADS) {
        int i = idx >> 6, n = idx & 63;
        float2 p = ((const float2*)&P[(i + 1) * PSTR])[n];
        float cr = ccs[2 * n], ci = ccs[2 * n + 1];
        float v0 = cr * p.x - ci * p.y;
        float v1 = -(cr * p.y + ci * p.x);
        u16 h0, l0, h1, l1;
        split_bf(v0, h0, l0);
        split_bf(v1, h1, l1);
        u32 off = (u32)(i * SB128 + 4 * n);
        *(u32*)(smem + OFF_VH + off) = (u32)h0 | ((u32)h1 << 16);
        *(u32*)(smem + OFF_VL + off) = (u32)l0 | ((u32)l1 << 16);
    }
    __syncthreads();

    // ---- G2: Y[64 x 128] = T*U^T (K64) + V*St^T (K128), 16 warps, 16x32 tiles ----
    {
        const int wm = wid & 3, wn = wid >> 2;
        float acc[4][4];
        #pragma unroll
        for (int nt = 0; nt < 4; ++nt)
            #pragma unroll
            for (int r = 0; r < 4; ++r) acc[nt][r] = 0.0f;

        #pragma unroll 1
        for (int prod = 0; prod < 3; ++prod) {
            u32 abase = sbase + ((prod == 2) ? OFF_TL : OFF_TH);
            u32 bbase = sbase + ((prod == 1) ? OFF_UL : OFF_UH);
            #pragma unroll
            for (int kt = 0; kt < 4; ++kt) {
                const int kb = kt * 32;
                u32 af[4], bf[4][2];
                {
                    int row0 = wm * 16;
                    u32 ad = abase + (u32)((row0 + (lane & 15)) * SB64 + kb + (lane >> 4) * 16);
                    ldsm_x4(ad, af[0], af[1], af[2], af[3]);
                }
                #pragma unroll
                for (int ntp = 0; ntp < 2; ++ntp) {
                    int n0 = wn * 32 + ntp * 16;
                    u32 bd = bbase + (u32)((n0 + ((lane >> 3) & 1) * 8 + (lane & 7)) * SB64
                                           + kb + (lane >> 4) * 16);
                    u32 q0, q1, q2, q3;
                    ldsm_x4(bd, q0, q1, q2, q3);
                    bf[2 * ntp][0] = q0; bf[2 * ntp][1] = q2;
                    bf[2 * ntp + 1][0] = q1; bf[2 * ntp + 1][1] = q3;
                }
                #pragma unroll
                for (int nt = 0; nt < 4; ++nt)
                    mma16816(acc[nt], af[0], af[1], af[2], af[3], bf[nt][0], bf[nt][1]);
            }
        }
        #pragma unroll 1
        for (int prod = 0; prod < 3; ++prod) {
            u32 abase = sbase + ((prod == 2) ? OFF_VL : OFF_VH);
            u32 bbase = sbase + ((prod == 1) ? OFF_STL : OFF_STH);
            #pragma unroll 1
            for (int kt = 0; kt < 8; ++kt) {
                const int kb = kt * 32;
                u32 af[4], bf[4][2];
                {
                    int row0 = wm * 16;
                    u32 ad = abase + (u32)((row0 + (lane & 15)) * SB128 + kb + (lane >> 4) * 16);
                    ldsm_x4(ad, af[0], af[1], af[2], af[3]);
                }
                #pragma unroll
                for (int ntp = 0; ntp < 2; ++ntp) {
                    int n0 = wn * 32 + ntp * 16;
                    u32 bd = bbase + (u32)((n0 + ((lane >> 3) & 1) * 8 + (lane & 7)) * SB128
                                           + kb + (lane >> 4) * 16);
                    u32 q0, q1, q2, q3;
                    ldsm_x4(bd, q0, q1, q2, q3);
                    bf[2 * ntp][0] = q0; bf[2 * ntp][1] = q2;
                    bf[2 * ntp + 1][0] = q1; bf[2 * ntp + 1][1] = q3;
                }
                #pragma unroll
                for (int nt = 0; nt < 4; ++nt)
                    mma16816(acc[nt], af[0], af[1], af[2], af[3], bf[nt][0], bf[nt][1]);
            }
        }

        // ---- stage Y into (dead) U region: [col][i], stride 68 floats ----
        __syncthreads();   // all warps done reading U/St panels
        float* Ysm = (float*)(smem + OFF_Y);
        #pragma unroll
        for (int nt = 0; nt < 4; ++nt)
            #pragma unroll
            for (int rg = 0; rg < 4; ++rg) {
                int i = wm * 16 + (lane >> 2) + ((rg >= 2) ? 8 : 0);
                int col = wn * 32 + nt * 8 + (lane & 3) * 2 + (rg & 1);
                Ysm[col * YSTR + i] = acc[nt][rg];
            }
    }
    __syncthreads();

    // ---- Epilogue: coalesced y = Y + D*u (float4) ----
    {
        const float Dh = Dv[h];
        const float* Ysm = (const float*)(smem + OFF_Y);
        const float4* u4 = (const float4*)u;
        float4* y4 = (float4*)y;
        for (int idx = tid; idx < 2048; idx += NTHREADS) {
            int b = idx >> 9, l4 = idx & 511;
            int c = (l4 >> 4) & 31, jq = l4 & 15;
            int col = b * 32 + c;
            float4 uv = u4[((size_t)b * HH + h) * 512 + (u32)l4];
            float4 yv = *(const float4*)&Ysm[col * YSTR + jq * 4];
            float4 ov;
            ov.x = yv.x + Dh * uv.x;
            ov.y = yv.y + Dh * uv.y;
            ov.z = yv.z + Dh * uv.z;
            ov.w = yv.w + Dh * uv.w;
            y4[((size_t)b * HH + h) * 512 + (u32)l4] = ov;
        }
    }
}

extern "C" void kernel_launch(void* const* d_in, const int* in_sizes, int n_in,
                              void* d_out, int out_size) {
    const float* u    = (const float*)d_in[0];
    const float* lnr  = (const float*)d_in[1];
    const float* im   = (const float*)d_in[2];
    const float* B_re = (const float*)d_in[3];
    const float* B_im = (const float*)d_in[4];
    const float* C_re = (const float*)d_in[5];
    const float* C_im = (const float*)d_in[6];
    const float* ldt  = (const float*)d_in[7];
    const float* Dv   = (const float*)d_in[8];
    float* y = (float*)d_out;

    static int attr_done = 0;
    if (!attr_done) {
        cudaFuncSetAttribute(ssm_mma_kernel,
                             cudaFuncAttributeMaxDynamicSharedMemorySize, SMEM_BYTES);
        attr_done = 1;
    }

    setup_kernel<<<(HH * NN + 255) / 256, 256>>>(lnr, im, B_re, B_im, C_re, C_im, ldt);
    ssm_mma_kernel<<<NBLK, NTHREADS, SMEM_BYTES>>>(u, Dv, y);
}